// round 6
// baseline (speedup 1.0000x reference)
#include <cuda_runtime.h>
#include <cstdint>

#define B_   8
#define CIN  64
#define COUT 8
#define H1   128
#define W1   128
#define H2   256
#define W2   256
#define PLANE (H2*W2)   /* 65536 */
#define NUM_ 8

// ---------------- scratch (device globals; no allocation allowed) ----------
__device__ float g_c1 [(size_t)B_*CIN *PLANE];  // conv1+BN+ReLU
__device__ float g_xf [(size_t)B_*COUT*PLANE];  // conv2+BN, thresholded
__device__ float g_rs [(size_t)B_*COUT*PLANE];  // row sums
__device__ float g_ws [(size_t)B_*COUT*PLANE];  // 5x5 window sums
__device__ float g_rm [(size_t)B_*COUT*PLANE];  // row max of ws
__device__ unsigned long long g_seg[B_*COUT*8*8]; // per-segment top-8 keys

// ---------------- packed f32x2 helpers --------------------------------------
__device__ __forceinline__ unsigned long long pk2(float lo, float hi) {
    unsigned long long r;
    asm("mov.b64 %0, {%1, %2};" : "=l"(r) : "f"(lo), "f"(hi));
    return r;
}
__device__ __forceinline__ void upk2(unsigned long long v, float& lo, float& hi) {
    asm("mov.b64 {%0, %1}, %2;" : "=f"(lo), "=f"(hi) : "l"(v));
}
#define FMA2(d, a, b) asm("fma.rn.f32x2 %0, %1, %2, %0;" : "+l"(d) : "l"(a), "l"(b))

// dynamic smem layout for conv1
#define C1_SW_BYTES   (CIN * 9 * 8 * 8)            /* 36864 */
#define C1_SIN_BYTES  (2 * 6 * 132 * 8)            /* 12672 */
#define C1_SMEM_TOTAL (C1_SW_BYTES + C1_SIN_BYTES + 128)  /* 49664 */

// ============================================================================
// conv1: fused bilinear-2x-upsample + conv3x3(64->64) + bias + BN + ReLU
// smem input tile stored as pre-duplicated f32x2 pairs -> Q via 3x LDS.128.
// ============================================================================
__global__ __launch_bounds__(256, 3) void k_conv1(
    const float* __restrict__ x,
    const float* __restrict__ w1, const float* __restrict__ b1,
    const float* __restrict__ gamma1, const float* __restrict__ beta1,
    const float* __restrict__ mean1, const float* __restrict__ var1)
{
    extern __shared__ __align__(16) unsigned char dsm[];
    unsigned long long (*s_w)[9][8] =
        (unsigned long long (*)[9][8])(dsm);
    unsigned long long (*s_in)[6][132] =
        (unsigned long long (*)[6][132])(dsm + C1_SW_BYTES);
    float* s_scale = (float*)(dsm + C1_SW_BYTES + C1_SIN_BYTES);
    float* s_shift = s_scale + 16;

    const int tid = threadIdx.x;
    const int xg = tid & 31;
    const int yg = (tid >> 5) & 3;
    const int cg = tid >> 7;
    const int bz  = blockIdx.z;
    const int b   = bz >> 2;
    const int co0 = (bz & 3) * 16;
    const int x0t = blockIdx.x * 128;
    const int y0t = blockIdx.y * 4;

    const float* xb = x + (size_t)b * CIN * (H1 * W1);

    for (int i = tid; i < CIN * 9 * 8; i += 256) {
        int cp = i & 7; int rest = i >> 3;
        int p = rest % 9; int ci = rest / 9;
        int coA = co0 + 2 * cp;
        float wa = w1[((size_t)coA       * CIN + ci) * 9 + p];
        float wb = w1[((size_t)(coA + 1) * CIN + ci) * 9 + p];
        s_w[ci][p][cp] = pk2(wa, wb);
    }
    if (tid < 16) {
        int co = co0 + tid;
        float a = gamma1[co] * rsqrtf(var1[co] + 1e-5f);
        s_scale[tid] = a;
        s_shift[tid] = fmaf(a, b1[co] - mean1[co], beta1[co]);
    }

    const bool runA = tid < 198;
    const int ur  = tid / 33;
    const int c0r = (tid - ur * 33) * 4;
    const int gy  = y0t + ur - 1;
    const int gx0 = x0t + c0r - 1;
    const int sy  = (gy - 1) >> 1;
    const int ro0 = min(max(sy, 0), H1 - 1) * W1;
    const int ro1 = min(max(sy + 1, 0), H1 - 1) * W1;
    const float wyv = (gy & 1) ? 0.25f : 0.75f;
    const int S   = (gx0 - 1) >> 1;
    const int cS0 = min(max(S, 0), W1 - 1);
    const int cS1 = min(max(S + 1, 0), W1 - 1);
    const int cS2 = min(max(S + 2, 0), W1 - 1);
    const bool rowOK = (gy >= 0) && (gy < H2);
    bool mok[4];
#pragma unroll
    for (int j = 0; j < 4; j++) {
        int gx = gx0 + j;
        mok[j] = rowOK && (gx >= 0) && (gx < W2);
    }

#define BILIN(buf, p0a, p0b, p0c, p1a, p1b, p1c) do {                         \
        float t0 = p0a + 0.25f * (p0b - p0a);                                 \
        float t1 = p0a + 0.75f * (p0b - p0a);                                 \
        float t2 = p0b + 0.25f * (p0c - p0b);                                 \
        float t3 = p0b + 0.75f * (p0c - p0b);                                 \
        float u0 = p1a + 0.25f * (p1b - p1a);                                 \
        float u1 = p1a + 0.75f * (p1b - p1a);                                 \
        float u2 = p1b + 0.25f * (p1c - p1b);                                 \
        float u3 = p1b + 0.75f * (p1c - p1b);                                 \
        float o0 = mok[0] ? (t0 + wyv * (u0 - t0)) : 0.f;                     \
        float o1 = mok[1] ? (t1 + wyv * (u1 - t1)) : 0.f;                     \
        float o2 = mok[2] ? (t2 + wyv * (u2 - t2)) : 0.f;                     \
        float o3 = mok[3] ? (t3 + wyv * (u3 - t3)) : 0.f;                     \
        ulonglong2 e0, e1;                                                    \
        e0.x = pk2(o0, o0); e0.y = pk2(o1, o1);                               \
        e1.x = pk2(o2, o2); e1.y = pk2(o3, o3);                               \
        *(ulonglong2*)&s_in[buf][ur][c0r]     = e0;                           \
        *(ulonglong2*)&s_in[buf][ur][c0r + 2] = e1;                           \
    } while (0)

    if (runA) {
        const float* xp = xb;
        float a0 = xp[ro0 + cS0], a1 = xp[ro0 + cS1], a2 = xp[ro0 + cS2];
        float b0 = xp[ro1 + cS0], b1v = xp[ro1 + cS1], b2 = xp[ro1 + cS2];
        BILIN(0, a0, a1, a2, b0, b1v, b2);
    }
    __syncthreads();

    unsigned long long acc[4][4];
#pragma unroll
    for (int q = 0; q < 4; q++)
#pragma unroll
        for (int j = 0; j < 4; j++) acc[q][j] = 0ull;

    for (int ci = 0; ci < CIN; ci++) {
        const int cur = ci & 1;

        float p0a, p0b, p0c, p1a, p1b, p1c;
        if (runA && ci < CIN - 1) {
            const float* xp = xb + ((size_t)(ci + 1) << 14);
            p0a = xp[ro0 + cS0]; p0b = xp[ro0 + cS1]; p0c = xp[ro0 + cS2];
            p1a = xp[ro1 + cS0]; p1b = xp[ro1 + cS1]; p1c = xp[ro1 + cS2];
        }

#pragma unroll
        for (int kr = 0; kr < 3; kr++) {
            const unsigned long long* row = &s_in[cur][yg + kr][4 * xg];
            ulonglong2 q01 = *(const ulonglong2*)row;
            ulonglong2 q23 = *(const ulonglong2*)(row + 2);
            ulonglong2 q45 = *(const ulonglong2*)(row + 4);
            unsigned long long Q[6] = {q01.x, q01.y, q23.x, q23.y, q45.x, q45.y};
#pragma unroll
            for (int kc = 0; kc < 3; kc++) {
                const ulonglong2* wrow =
                    (const ulonglong2*)&s_w[ci][kr * 3 + kc][cg * 4];
                ulonglong2 wA = wrow[0];
                ulonglong2 wB = wrow[1];
#pragma unroll
                for (int q = 0; q < 4; q++) {
                    unsigned long long iv = Q[kc + q];
                    FMA2(acc[q][0], iv, wA.x);
                    FMA2(acc[q][1], iv, wA.y);
                    FMA2(acc[q][2], iv, wB.x);
                    FMA2(acc[q][3], iv, wB.y);
                }
            }
        }

        if (runA && ci < CIN - 1) {
            BILIN(cur ^ 1, p0a, p0b, p0c, p1a, p1b, p1c);
        }
        __syncthreads();
    }
#undef BILIN

    const int oy = y0t + yg;
    const int ox = x0t + 4 * xg;
    float* outb = g_c1 + (((size_t)b * CIN + co0 + 8 * cg) << 16) + (oy << 8) + ox;
#pragma unroll
    for (int j = 0; j < 4; j++) {
        float va[4], vb[4];
#pragma unroll
        for (int q = 0; q < 4; q++) upk2(acc[q][j], va[q], vb[q]);
        const int cr = 8 * cg + 2 * j;
        const float sa = s_scale[cr],     sha = s_shift[cr];
        const float sb = s_scale[cr + 1], shb = s_shift[cr + 1];
        float4 oa, ob;
        oa.x = fmaxf(fmaf(sa, va[0], sha), 0.f);
        oa.y = fmaxf(fmaf(sa, va[1], sha), 0.f);
        oa.z = fmaxf(fmaf(sa, va[2], sha), 0.f);
        oa.w = fmaxf(fmaf(sa, va[3], sha), 0.f);
        ob.x = fmaxf(fmaf(sb, vb[0], shb), 0.f);
        ob.y = fmaxf(fmaf(sb, vb[1], shb), 0.f);
        ob.z = fmaxf(fmaf(sb, vb[2], shb), 0.f);
        ob.w = fmaxf(fmaf(sb, vb[3], shb), 0.f);
        *(float4*)(outb + ((size_t)(2 * j)     << 16)) = oa;
        *(float4*)(outb + ((size_t)(2 * j + 1) << 16)) = ob;
    }
}

// ---------------- conv1x1(64->8) + BN + threshold + fused row-sum -----------
// block = (b, 4-row group); thread = 1 row x 4 cols x 8 co. FFMA2, LDG.128.
__global__ __launch_bounds__(256) void k_conv2rs(
    const float* __restrict__ w2,
    const float* __restrict__ gamma2, const float* __restrict__ beta2,
    const float* __restrict__ mean2, const float* __restrict__ var2)
{
    __shared__ unsigned long long s_wp[8][64];
    __shared__ float s_scale[8], s_shift[8];
    __shared__ float s_xf[8][4][264];   // data at idx 4..259; halo 2,3,260,261
    const int tid = threadIdx.x;
    const int b  = blockIdx.x >> 6;
    const int y0 = (blockIdx.x & 63) * 4;
    const int r = tid >> 6;
    const int col0 = (tid & 63) * 4;

    if (tid < 8) {
        float a = gamma2[tid] * rsqrtf(var2[tid] + 1e-5f);
        s_scale[tid] = a;
        s_shift[tid] = beta2[tid] - a * mean2[tid];
    }
    for (int i = tid; i < 512; i += 256) {
        int co = i >> 6, ci = i & 63;
        float w = w2[co * 64 + ci];
        s_wp[co][ci] = pk2(w, w);
    }
    if (tid < 128) {
        int co = tid >> 4, rr = (tid >> 2) & 3, which = tid & 3;
        const int idxs[4] = {2, 3, 260, 261};
        s_xf[co][rr][idxs[which]] = 0.f;
    }
    __syncthreads();

    const ulonglong2* c1 = (const ulonglong2*)
        (g_c1 + ((size_t)b * CIN << 16) + ((size_t)(y0 + r) << 8) + col0);
    unsigned long long a01[8], a23[8];
#pragma unroll
    for (int co = 0; co < 8; co++) { a01[co] = 0ull; a23[co] = 0ull; }
#pragma unroll 8
    for (int ci = 0; ci < CIN; ci++) {
        ulonglong2 v = c1[(size_t)ci * 16384];
#pragma unroll
        for (int co = 0; co < 8; co++) {
            unsigned long long w = s_wp[co][ci];
            FMA2(a01[co], v.x, w);
            FMA2(a23[co], v.y, w);
        }
    }

    const size_t rowoff = ((size_t)(y0 + r) << 8) + col0;
#pragma unroll
    for (int co = 0; co < 8; co++) {
        float f0, f1, f2, f3;
        upk2(a01[co], f0, f1);
        upk2(a23[co], f2, f3);
        const float sc = s_scale[co], sh = s_shift[co];
        float o0 = fmaf(sc, f0, sh), o1 = fmaf(sc, f1, sh);
        float o2 = fmaf(sc, f2, sh), o3 = fmaf(sc, f3, sh);
        float4 xf;
        xf.x = (o0 > 1.0f) ? o0 : 0.f;
        xf.y = (o1 > 1.0f) ? o1 : 0.f;
        xf.z = (o2 > 1.0f) ? o2 : 0.f;
        xf.w = (o3 > 1.0f) ? o3 : 0.f;
        *(float4*)(g_xf + (((size_t)b * COUT + co) << 16) + rowoff) = xf;
        *(float4*)&s_xf[co][r][col0 + 4] = xf;
    }
    __syncthreads();

#pragma unroll
    for (int co = 0; co < 8; co++) {
        const float* f = &s_xf[co][r][col0 + 2];
        float4 s;
        s.x = f[0] + f[1] + f[2] + f[3] + f[4];
        s.y = f[1] + f[2] + f[3] + f[4] + f[5];
        s.z = f[2] + f[3] + f[4] + f[5] + f[6];
        s.w = f[3] + f[4] + f[5] + f[6] + f[7];
        *(float4*)(g_rs + (((size_t)b * COUT + co) << 16) + rowoff) = s;
    }
}

// ---------------- fused column-sum (-> ws) + row-max of ws ------------------
// block = (plane, 4-row group); 8-row smem stage.
__global__ __launch_bounds__(256) void k_wsmax() {
    __shared__ float s_rs[8][256];
    __shared__ float s_ws[4][264];   // data 2..257; halo 0,1,258,259 = -1
    const int tid = threadIdx.x;
    const int pl = blockIdx.x >> 6;
    const int y0 = (blockIdx.x & 63) * 4;
    const float* rs = g_rs + ((size_t)pl << 16);

#pragma unroll
    for (int i = 0; i < 8; i++) {
        int row = y0 - 2 + i;
        s_rs[i][tid] = (row >= 0 && row < 256) ? rs[(row << 8) + tid] : 0.f;
    }
    if (tid < 16) {
        int rr = tid >> 2, which = tid & 3;
        const int idxs[4] = {0, 1, 258, 259};
        s_ws[rr][idxs[which]] = -1.f;
    }
    __syncthreads();

#pragma unroll
    for (int j = 0; j < 4; j++) {
        float s = s_rs[j][tid] + s_rs[j + 1][tid] + s_rs[j + 2][tid]
                + s_rs[j + 3][tid] + s_rs[j + 4][tid];
        g_ws[((size_t)pl << 16) + ((y0 + j) << 8) + tid] = s;
        s_ws[j][tid + 2] = s;
    }
    __syncthreads();

#pragma unroll
    for (int j = 0; j < 4; j++) {
        const float* w = &s_ws[j][tid];
        float m = fmaxf(fmaxf(fmaxf(w[0], w[1]), fmaxf(w[2], w[3])), w[4]);
        g_rm[((size_t)pl << 16) + ((y0 + j) << 8) + tid] = m;
    }
}

// ---------------- top-k stage 1: per-segment top-8 ---------------------------
// smem-staged rm tile; ws prefetch depth 2. key = (bits<<32) | ~pos.
__global__ __launch_bounds__(256) void k_topk1() {
    __shared__ __align__(16) float s_rm[36][256];      // 36 KB; aliased below
    unsigned long long* s_keys = (unsigned long long*)&s_rm[0][0];
    const int bid = blockIdx.x;
    const int bc = bid >> 3;
    const int seg = bid & 7;
    const int y0 = seg * 32;
    const int x = threadIdx.x;
    const float* ws = g_ws + (size_t)bc * PLANE;
    const float* rm = g_rm + (size_t)bc * PLANE;

#pragma unroll
    for (int i = 0; i < 36; i++) {
        int row = y0 - 2 + i;
        s_rm[i][x] = (row >= 0 && row < 256) ? rm[(row << 8) + x] : -1.f;
    }
    __syncthreads();

    unsigned long long k[8];
#pragma unroll
    for (int j = 0; j < 8; j++) k[j] = 0ull;

    float w0 = s_rm[0][x], w1 = s_rm[1][x], w2 = s_rm[2][x], w3 = s_rm[3][x], w4;
    float v0 = ws[(y0 << 8) + x];
    float v1 = ws[((y0 + 1) << 8) + x];
    for (int i = 0; i < 32; i++) {
        w4 = s_rm[i + 4][x];
        float m = fmaxf(fmaxf(fmaxf(w0, w1), fmaxf(w2, w3)), w4);
        float v = v0;
        v0 = v1;
        if (i + 2 < 32) v1 = ws[((y0 + i + 2) << 8) + x];
        if (v == m) {
            unsigned pos = (unsigned)(((y0 + i) << 8) + x);
            unsigned long long key =
                ((unsigned long long)__float_as_uint(v) << 32) | (unsigned)(~pos);
            if (key > k[7]) {
                int p = 7;
#pragma unroll
                for (int q = 7; q > 0; q--) {
                    if (key > k[q - 1]) { k[q] = k[q - 1]; p = q - 1; }
                }
                k[p] = key;
            }
        }
        w0 = w1; w1 = w2; w2 = w3; w3 = w4;
    }
    __syncthreads();   // done reading s_rm; safe to alias

#pragma unroll
    for (int j = 0; j < 8; j++) s_keys[x * 8 + j] = k[j];
    __syncthreads();

    for (int off = 128; off > 0; off >>= 1) {
        if (x < off) {
            unsigned long long* a = &s_keys[x * 8];
            unsigned long long* b = &s_keys[(x + off) * 8];
            unsigned long long out[8];
            int i = 0, j = 0;
#pragma unroll
            for (int t = 0; t < 8; t++)
                out[t] = (a[i] >= b[j]) ? a[i++] : b[j++];
#pragma unroll
            for (int t = 0; t < 8; t++) a[t] = out[t];
        }
        __syncthreads();
    }
    if (x < 8) g_seg[bid * 8 + x] = s_keys[x];
}

// ---------------- top-k stage 2 (merge 8x8 keys) + fused gather --------------
__global__ __launch_bounds__(64) void k_topk2(float* __restrict__ out) {
    __shared__ unsigned long long s[64];
    __shared__ unsigned long long top[8];
    const int bc = blockIdx.x;
    const int tid = threadIdx.x;

    s[tid] = g_seg[bc * 64 + tid];
    __syncthreads();

    if (tid == 0) {
        unsigned long long k[8];
#pragma unroll
        for (int j = 0; j < 8; j++) k[j] = 0ull;
        for (int i = 0; i < 64; i++) {
            unsigned long long key = s[i];
            if (key > k[7]) {
                int p = 7;
#pragma unroll
                for (int q = 7; q > 0; q--) {
                    if (key > k[q - 1]) { k[q] = k[q - 1]; p = q - 1; }
                }
                k[p] = key;
            }
        }
#pragma unroll
        for (int j = 0; j < 8; j++) top[j] = k[j];
    }
    __syncthreads();

    if (tid < 8) {
        unsigned pos = ~(unsigned)(top[tid] & 0xFFFFFFFFull);
        int h = pos >> 8, w = pos & 255;
        const int gid = bc * 8 + tid;
        const float* xf = g_xf + (size_t)bc * PLANE;
        float* po = out + gid * 25;
#pragma unroll
        for (int dy = 0; dy < 5; dy++) {
            int yy = h + dy - 2;
#pragma unroll
            for (int dx = 0; dx < 5; dx++) {
                int xx = w + dx - 2;
                float v = 0.f;
                if (yy >= 0 && yy < 256 && xx >= 0 && xx < 256) v = xf[yy * 256 + xx];
                po[dy * 5 + dx] = v;
            }
        }
        float* pp = out + B_ * COUT * NUM_ * 25 + gid * 4;
        pp[0] = (float)min(max(w - 2, 0), 255);
        pp[1] = (float)min(max(h - 2, 0), 255);
        pp[2] = (float)min(max(w + 2, 0), 255);
        pp[3] = (float)min(max(h + 2, 0), 255);
    }
}

// ---------------- launch ------------------------------------------------------
extern "C" void kernel_launch(void* const* d_in, const int* in_sizes, int n_in,
                              void* d_out, int out_size) {
    const float* x      = (const float*)d_in[0];
    const float* w1     = (const float*)d_in[1];
    const float* b1     = (const float*)d_in[2];
    const float* gamma1 = (const float*)d_in[3];
    const float* beta1  = (const float*)d_in[4];
    const float* mean1  = (const float*)d_in[5];
    const float* var1   = (const float*)d_in[6];
    const float* w2     = (const float*)d_in[7];
    const float* gamma2 = (const float*)d_in[8];
    const float* beta2  = (const float*)d_in[9];
    const float* mean2  = (const float*)d_in[10];
    const float* var2   = (const float*)d_in[11];
    float* out = (float*)d_out;

    cudaFuncSetAttribute(k_conv1, cudaFuncAttributeMaxDynamicSharedMemorySize,
                         C1_SMEM_TOTAL);

    dim3 cg(2, 64, B_ * 4);
    k_conv1<<<cg, 256, C1_SMEM_TOTAL>>>(x, w1, b1, gamma1, beta1, mean1, var1);

    k_conv2rs<<<B_ * 64, 256>>>(w2, gamma2, beta2, mean2, var2);
    k_wsmax<<<B_ * COUT * 64, 256>>>();

    k_topk1<<<B_ * COUT * 8, 256>>>();
    k_topk2<<<B_ * COUT, 64>>>(out);
}

// round 7
// speedup vs baseline: 1.2954x; 1.2954x over previous
#include <cuda_runtime.h>
#include <cstdint>

#define B_   8
#define CIN  64
#define COUT 8
#define H1   128
#define W1   128
#define H2   256
#define W2   256
#define PLANE (H2*W2)   /* 65536 */
#define NUM_ 8
#define NSEG 16

// ---------------- scratch (device globals; no allocation allowed) ----------
__device__ float g_c1 [(size_t)B_*CIN *PLANE];  // conv1+BN+ReLU
__device__ float g_xf [(size_t)B_*COUT*PLANE];  // conv2+BN, thresholded
__device__ float g_rs [(size_t)B_*COUT*PLANE];  // row sums
__device__ float g_ws [(size_t)B_*COUT*PLANE];  // 5x5 window sums
__device__ float g_rm [(size_t)B_*COUT*PLANE];  // row max of ws
__device__ unsigned long long g_seg[B_*COUT*NSEG*8]; // per-segment top-8 keys

// ---------------- packed f32x2 helpers --------------------------------------
__device__ __forceinline__ unsigned long long pk2(float lo, float hi) {
    unsigned long long r;
    asm("mov.b64 %0, {%1, %2};" : "=l"(r) : "f"(lo), "f"(hi));
    return r;
}
__device__ __forceinline__ void upk2(unsigned long long v, float& lo, float& hi) {
    asm("mov.b64 {%0, %1}, %2;" : "=f"(lo), "=f"(hi) : "l"(v));
}
#define FMA2(d, a, b) asm("fma.rn.f32x2 %0, %1, %2, %0;" : "+l"(d) : "l"(a), "l"(b))

// ============================================================================
// conv1: fused bilinear-2x-upsample + conv3x3(64->64) + bias + BN + ReLU
// (round-5 configuration: static smem, float tile, register-side packing)
// ============================================================================
__global__ __launch_bounds__(256, 3) void k_conv1(
    const float* __restrict__ x,
    const float* __restrict__ w1, const float* __restrict__ b1,
    const float* __restrict__ gamma1, const float* __restrict__ beta1,
    const float* __restrict__ mean1, const float* __restrict__ var1)
{
    __shared__ unsigned long long s_w[CIN][9][8];  // [ci][tap][co-pair]
    __shared__ float s_in[2][6][136];
    __shared__ float s_scale[16], s_shift[16];

    const int tid = threadIdx.x;
    const int xg = tid & 31;
    const int yg = (tid >> 5) & 3;
    const int cg = tid >> 7;
    const int bz  = blockIdx.z;
    const int b   = bz >> 2;
    const int co0 = (bz & 3) * 16;
    const int x0t = blockIdx.x * 128;
    const int y0t = blockIdx.y * 4;

    const float* xb = x + (size_t)b * CIN * (H1 * W1);

    for (int i = tid; i < CIN * 9 * 8; i += 256) {
        int cp = i & 7; int rest = i >> 3;
        int p = rest % 9; int ci = rest / 9;
        int coA = co0 + 2 * cp;
        float wa = w1[((size_t)coA       * CIN + ci) * 9 + p];
        float wb = w1[((size_t)(coA + 1) * CIN + ci) * 9 + p];
        s_w[ci][p][cp] = pk2(wa, wb);
    }
    if (tid < 16) {
        int co = co0 + tid;
        float a = gamma1[co] * rsqrtf(var1[co] + 1e-5f);
        s_scale[tid] = a;
        s_shift[tid] = fmaf(a, b1[co] - mean1[co], beta1[co]);
    }

    const bool runA = tid < 198;
    const int ur  = tid / 33;
    const int c0r = (tid - ur * 33) * 4;
    const int gy  = y0t + ur - 1;
    const int gx0 = x0t + c0r - 1;
    const int sy  = (gy - 1) >> 1;
    const int ro0 = min(max(sy, 0), H1 - 1) * W1;
    const int ro1 = min(max(sy + 1, 0), H1 - 1) * W1;
    const float wyv = (gy & 1) ? 0.25f : 0.75f;
    const int S   = (gx0 - 1) >> 1;
    const int cS0 = min(max(S, 0), W1 - 1);
    const int cS1 = min(max(S + 1, 0), W1 - 1);
    const int cS2 = min(max(S + 2, 0), W1 - 1);
    const bool rowOK = (gy >= 0) && (gy < H2);
    bool mok[4];
#pragma unroll
    for (int j = 0; j < 4; j++) {
        int gx = gx0 + j;
        mok[j] = rowOK && (gx >= 0) && (gx < W2);
    }

#define BILIN(buf, p0a, p0b, p0c, p1a, p1b, p1c) do {                         \
        float t0 = p0a + 0.25f * (p0b - p0a);                                 \
        float t1 = p0a + 0.75f * (p0b - p0a);                                 \
        float t2 = p0b + 0.25f * (p0c - p0b);                                 \
        float t3 = p0b + 0.75f * (p0c - p0b);                                 \
        float u0 = p1a + 0.25f * (p1b - p1a);                                 \
        float u1 = p1a + 0.75f * (p1b - p1a);                                 \
        float u2 = p1b + 0.25f * (p1c - p1b);                                 \
        float u3 = p1b + 0.75f * (p1c - p1b);                                 \
        float4 o;                                                             \
        o.x = mok[0] ? (t0 + wyv * (u0 - t0)) : 0.f;                          \
        o.y = mok[1] ? (t1 + wyv * (u1 - t1)) : 0.f;                          \
        o.z = mok[2] ? (t2 + wyv * (u2 - t2)) : 0.f;                          \
        o.w = mok[3] ? (t3 + wyv * (u3 - t3)) : 0.f;                          \
        *(float4*)&s_in[buf][ur][c0r] = o;                                    \
    } while (0)

    if (runA) {
        const float* xp = xb;
        float a0 = xp[ro0 + cS0], a1 = xp[ro0 + cS1], a2 = xp[ro0 + cS2];
        float b0 = xp[ro1 + cS0], b1v = xp[ro1 + cS1], b2 = xp[ro1 + cS2];
        BILIN(0, a0, a1, a2, b0, b1v, b2);
    }
    __syncthreads();

    unsigned long long acc[4][4];
#pragma unroll
    for (int q = 0; q < 4; q++)
#pragma unroll
        for (int j = 0; j < 4; j++) acc[q][j] = 0ull;

    for (int ci = 0; ci < CIN; ci++) {
        const int cur = ci & 1;

        float p0a, p0b, p0c, p1a, p1b, p1c;
        if (runA && ci < CIN - 1) {
            const float* xp = xb + ((size_t)(ci + 1) << 14);
            p0a = xp[ro0 + cS0]; p0b = xp[ro0 + cS1]; p0c = xp[ro0 + cS2];
            p1a = xp[ro1 + cS0]; p1b = xp[ro1 + cS1]; p1c = xp[ro1 + cS2];
        }

#pragma unroll
        for (int kr = 0; kr < 3; kr++) {
            const float* row = &s_in[cur][yg + kr][4 * xg];
            float4 F = *(const float4*)row;
            float2 G = *(const float2*)(row + 4);
            unsigned long long Q[6];
            Q[0] = pk2(F.x, F.x);
            Q[1] = pk2(F.y, F.y);
            Q[2] = pk2(F.z, F.z);
            Q[3] = pk2(F.w, F.w);
            Q[4] = pk2(G.x, G.x);
            Q[5] = pk2(G.y, G.y);
#pragma unroll
            for (int kc = 0; kc < 3; kc++) {
                const ulonglong2* wrow =
                    (const ulonglong2*)&s_w[ci][kr * 3 + kc][cg * 4];
                ulonglong2 wA = wrow[0];
                ulonglong2 wB = wrow[1];
#pragma unroll
                for (int q = 0; q < 4; q++) {
                    unsigned long long iv = Q[kc + q];
                    FMA2(acc[q][0], iv, wA.x);
                    FMA2(acc[q][1], iv, wA.y);
                    FMA2(acc[q][2], iv, wB.x);
                    FMA2(acc[q][3], iv, wB.y);
                }
            }
        }

        if (runA && ci < CIN - 1) {
            BILIN(cur ^ 1, p0a, p0b, p0c, p1a, p1b, p1c);
        }
        __syncthreads();
    }
#undef BILIN

    const int oy = y0t + yg;
    const int ox = x0t + 4 * xg;
    float* outb = g_c1 + (((size_t)b * CIN + co0 + 8 * cg) << 16) + (oy << 8) + ox;
#pragma unroll
    for (int j = 0; j < 4; j++) {
        float va[4], vb[4];
#pragma unroll
        for (int q = 0; q < 4; q++) upk2(acc[q][j], va[q], vb[q]);
        const int cr = 8 * cg + 2 * j;
        const float sa = s_scale[cr],     sha = s_shift[cr];
        const float sb = s_scale[cr + 1], shb = s_shift[cr + 1];
        float4 oa, ob;
        oa.x = fmaxf(fmaf(sa, va[0], sha), 0.f);
        oa.y = fmaxf(fmaf(sa, va[1], sha), 0.f);
        oa.z = fmaxf(fmaf(sa, va[2], sha), 0.f);
        oa.w = fmaxf(fmaf(sa, va[3], sha), 0.f);
        ob.x = fmaxf(fmaf(sb, vb[0], shb), 0.f);
        ob.y = fmaxf(fmaf(sb, vb[1], shb), 0.f);
        ob.z = fmaxf(fmaf(sb, vb[2], shb), 0.f);
        ob.w = fmaxf(fmaf(sb, vb[3], shb), 0.f);
        *(float4*)(outb + ((size_t)(2 * j)     << 16)) = oa;
        *(float4*)(outb + ((size_t)(2 * j + 1) << 16)) = ob;
    }
}

// ---------------- conv1x1(64->8) + BN + threshold + fused row-sum -----------
// block = (b, 4-row group); thread = 1 row x 4 cols x 8 co. FFMA2, LDG.128.
__global__ __launch_bounds__(256) void k_conv2rs(
    const float* __restrict__ w2,
    const float* __restrict__ gamma2, const float* __restrict__ beta2,
    const float* __restrict__ mean2, const float* __restrict__ var2)
{
    __shared__ unsigned long long s_wp[8][64];
    __shared__ float s_scale[8], s_shift[8];
    __shared__ float s_xf[8][4][264];   // data at idx 4..259; halo 2,3,260,261
    const int tid = threadIdx.x;
    const int b  = blockIdx.x >> 6;
    const int y0 = (blockIdx.x & 63) * 4;
    const int r = tid >> 6;
    const int col0 = (tid & 63) * 4;

    if (tid < 8) {
        float a = gamma2[tid] * rsqrtf(var2[tid] + 1e-5f);
        s_scale[tid] = a;
        s_shift[tid] = beta2[tid] - a * mean2[tid];
    }
    for (int i = tid; i < 512; i += 256) {
        int co = i >> 6, ci = i & 63;
        float w = w2[co * 64 + ci];
        s_wp[co][ci] = pk2(w, w);
    }
    if (tid < 128) {
        int co = tid >> 4, rr = (tid >> 2) & 3, which = tid & 3;
        const int idxs[4] = {2, 3, 260, 261};
        s_xf[co][rr][idxs[which]] = 0.f;
    }
    __syncthreads();

    const ulonglong2* c1 = (const ulonglong2*)
        (g_c1 + ((size_t)b * CIN << 16) + ((size_t)(y0 + r) << 8) + col0);
    unsigned long long a01[8], a23[8];
#pragma unroll
    for (int co = 0; co < 8; co++) { a01[co] = 0ull; a23[co] = 0ull; }
#pragma unroll 8
    for (int ci = 0; ci < CIN; ci++) {
        ulonglong2 v = c1[(size_t)ci * 16384];
#pragma unroll
        for (int co = 0; co < 8; co++) {
            unsigned long long w = s_wp[co][ci];
            FMA2(a01[co], v.x, w);
            FMA2(a23[co], v.y, w);
        }
    }

    const size_t rowoff = ((size_t)(y0 + r) << 8) + col0;
#pragma unroll
    for (int co = 0; co < 8; co++) {
        float f0, f1, f2, f3;
        upk2(a01[co], f0, f1);
        upk2(a23[co], f2, f3);
        const float sc = s_scale[co], sh = s_shift[co];
        float o0 = fmaf(sc, f0, sh), o1 = fmaf(sc, f1, sh);
        float o2 = fmaf(sc, f2, sh), o3 = fmaf(sc, f3, sh);
        float4 xf;
        xf.x = (o0 > 1.0f) ? o0 : 0.f;
        xf.y = (o1 > 1.0f) ? o1 : 0.f;
        xf.z = (o2 > 1.0f) ? o2 : 0.f;
        xf.w = (o3 > 1.0f) ? o3 : 0.f;
        *(float4*)(g_xf + (((size_t)b * COUT + co) << 16) + rowoff) = xf;
        *(float4*)&s_xf[co][r][col0 + 4] = xf;
    }
    __syncthreads();

#pragma unroll
    for (int co = 0; co < 8; co++) {
        const float* f = &s_xf[co][r][col0 + 2];
        float4 s;
        s.x = f[0] + f[1] + f[2] + f[3] + f[4];
        s.y = f[1] + f[2] + f[3] + f[4] + f[5];
        s.z = f[2] + f[3] + f[4] + f[5] + f[6];
        s.w = f[3] + f[4] + f[5] + f[6] + f[7];
        *(float4*)(g_rs + (((size_t)b * COUT + co) << 16) + rowoff) = s;
    }
}

// ---------------- fused column-sum (-> ws) + row-max of ws ------------------
// block = (plane, 4-row group); 8-row smem stage.
__global__ __launch_bounds__(256) void k_wsmax() {
    __shared__ float s_rs[8][256];
    __shared__ float s_ws[4][264];   // data 2..257; halo 0,1,258,259 = -1
    const int tid = threadIdx.x;
    const int pl = blockIdx.x >> 6;
    const int y0 = (blockIdx.x & 63) * 4;
    const float* rs = g_rs + ((size_t)pl << 16);

#pragma unroll
    for (int i = 0; i < 8; i++) {
        int row = y0 - 2 + i;
        s_rs[i][tid] = (row >= 0 && row < 256) ? rs[(row << 8) + tid] : 0.f;
    }
    if (tid < 16) {
        int rr = tid >> 2, which = tid & 3;
        const int idxs[4] = {0, 1, 258, 259};
        s_ws[rr][idxs[which]] = -1.f;
    }
    __syncthreads();

#pragma unroll
    for (int j = 0; j < 4; j++) {
        float s = s_rs[j][tid] + s_rs[j + 1][tid] + s_rs[j + 2][tid]
                + s_rs[j + 3][tid] + s_rs[j + 4][tid];
        g_ws[((size_t)pl << 16) + ((y0 + j) << 8) + tid] = s;
        s_ws[j][tid + 2] = s;
    }
    __syncthreads();

#pragma unroll
    for (int j = 0; j < 4; j++) {
        const float* w = &s_ws[j][tid];
        float m = fmaxf(fmaxf(fmaxf(w[0], w[1]), fmaxf(w[2], w[3])), w[4]);
        g_rm[((size_t)pl << 16) + ((y0 + j) << 8) + tid] = m;
    }
}

// ---------------- top-k stage 1: per-segment top-8 (16 segments of 16 rows) --
// smem-staged rm tile; ws prefetch depth 2. key = (bits<<32) | ~pos.
__global__ __launch_bounds__(256) void k_topk1() {
    __shared__ __align__(16) float s_rm[20][256];      // 20 KB; aliased below
    unsigned long long* s_keys = (unsigned long long*)&s_rm[0][0]; // 16 KB
    const int bid = blockIdx.x;
    const int bc = bid >> 4;
    const int seg = bid & 15;
    const int y0 = seg * 16;
    const int x = threadIdx.x;
    const float* ws = g_ws + (size_t)bc * PLANE;
    const float* rm = g_rm + (size_t)bc * PLANE;

#pragma unroll
    for (int i = 0; i < 20; i++) {
        int row = y0 - 2 + i;
        s_rm[i][x] = (row >= 0 && row < 256) ? rm[(row << 8) + x] : -1.f;
    }
    __syncthreads();

    unsigned long long k[8];
#pragma unroll
    for (int j = 0; j < 8; j++) k[j] = 0ull;

    float w0 = s_rm[0][x], w1 = s_rm[1][x], w2 = s_rm[2][x], w3 = s_rm[3][x], w4;
    float v0 = ws[(y0 << 8) + x];
    float v1 = ws[((y0 + 1) << 8) + x];
#pragma unroll
    for (int i = 0; i < 16; i++) {
        w4 = s_rm[i + 4][x];
        float m = fmaxf(fmaxf(fmaxf(w0, w1), fmaxf(w2, w3)), w4);
        float v = v0;
        v0 = v1;
        if (i + 2 < 16) v1 = ws[((y0 + i + 2) << 8) + x];
        if (v == m) {
            unsigned pos = (unsigned)(((y0 + i) << 8) + x);
            unsigned long long key =
                ((unsigned long long)__float_as_uint(v) << 32) | (unsigned)(~pos);
            if (key > k[7]) {
                int p = 7;
#pragma unroll
                for (int q = 7; q > 0; q--) {
                    if (key > k[q - 1]) { k[q] = k[q - 1]; p = q - 1; }
                }
                k[p] = key;
            }
        }
        w0 = w1; w1 = w2; w2 = w3; w3 = w4;
    }
    __syncthreads();   // done reading s_rm; safe to alias

#pragma unroll
    for (int j = 0; j < 8; j++) s_keys[x * 8 + j] = k[j];
    __syncthreads();

    for (int off = 128; off > 0; off >>= 1) {
        if (x < off) {
            unsigned long long* a = &s_keys[x * 8];
            unsigned long long* b = &s_keys[(x + off) * 8];
            unsigned long long out[8];
            int i = 0, j = 0;
#pragma unroll
            for (int t = 0; t < 8; t++)
                out[t] = (a[i] >= b[j]) ? a[i++] : b[j++];
#pragma unroll
            for (int t = 0; t < 8; t++) a[t] = out[t];
        }
        __syncthreads();
    }
    if (x < 8) g_seg[bid * 8 + x] = s_keys[x];
}

// ---------------- top-k stage 2 (merge NSEG*8 keys) + fused gather ----------
__global__ __launch_bounds__(128) void k_topk2(float* __restrict__ out) {
    __shared__ unsigned long long s[NSEG * 8];
    __shared__ unsigned long long top[8];
    const int bc = blockIdx.x;
    const int tid = threadIdx.x;

    s[tid] = g_seg[bc * (NSEG * 8) + tid];
    __syncthreads();

    if (tid == 0) {
        unsigned long long k[8];
#pragma unroll
        for (int j = 0; j < 8; j++) k[j] = 0ull;
        for (int i = 0; i < NSEG * 8; i++) {
            unsigned long long key = s[i];
            if (key > k[7]) {
                int p = 7;
#pragma unroll
                for (int q = 7; q > 0; q--) {
                    if (key > k[q - 1]) { k[q] = k[q - 1]; p = q - 1; }
                }
                k[p] = key;
            }
        }
#pragma unroll
        for (int j = 0; j < 8; j++) top[j] = k[j];
    }
    __syncthreads();

    if (tid < 8) {
        unsigned pos = ~(unsigned)(top[tid] & 0xFFFFFFFFull);
        int h = pos >> 8, w = pos & 255;
        const int gid = bc * 8 + tid;
        const float* xf = g_xf + (size_t)bc * PLANE;
        float* po = out + gid * 25;
#pragma unroll
        for (int dy = 0; dy < 5; dy++) {
            int yy = h + dy - 2;
#pragma unroll
            for (int dx = 0; dx < 5; dx++) {
                int xx = w + dx - 2;
                float v = 0.f;
                if (yy >= 0 && yy < 256 && xx >= 0 && xx < 256) v = xf[yy * 256 + xx];
                po[dy * 5 + dx] = v;
            }
        }
        float* pp = out + B_ * COUT * NUM_ * 25 + gid * 4;
        pp[0] = (float)min(max(w - 2, 0), 255);
        pp[1] = (float)min(max(h - 2, 0), 255);
        pp[2] = (float)min(max(w + 2, 0), 255);
        pp[3] = (float)min(max(h + 2, 0), 255);
    }
}

// ---------------- launch ------------------------------------------------------
extern "C" void kernel_launch(void* const* d_in, const int* in_sizes, int n_in,
                              void* d_out, int out_size) {
    const float* x      = (const float*)d_in[0];
    const float* w1     = (const float*)d_in[1];
    const float* b1     = (const float*)d_in[2];
    const float* gamma1 = (const float*)d_in[3];
    const float* beta1  = (const float*)d_in[4];
    const float* mean1  = (const float*)d_in[5];
    const float* var1   = (const float*)d_in[6];
    const float* w2     = (const float*)d_in[7];
    const float* gamma2 = (const float*)d_in[8];
    const float* beta2  = (const float*)d_in[9];
    const float* mean2  = (const float*)d_in[10];
    const float* var2   = (const float*)d_in[11];
    float* out = (float*)d_out;

    dim3 cg(2, 64, B_ * 4);
    k_conv1<<<cg, 256>>>(x, w1, b1, gamma1, beta1, mean1, var1);

    k_conv2rs<<<B_ * 64, 256>>>(w2, gamma2, beta2, mean2, var2);
    k_wsmax<<<B_ * COUT * 64, 256>>>();

    k_topk1<<<B_ * COUT * NSEG, 256>>>();
    k_topk2<<<B_ * COUT, NSEG * 8>>>(out);
}